// round 12
// baseline (speedup 1.0000x reference)
#include <cuda_runtime.h>
#include <math.h>

#define BATCH    8
#define NSRC     4096
#define MTGT     4096
#define TPB      128
#define SPT      4                       // sources per thread
#define SRC_PER_BLK (TPB * SPT)          // 512
#define NCHUNK   (NSRC / SRC_PER_BLK)    // 8
#define TSPLIT   16                      // target slices
#define MSLICE   (MTGT / TSPLIT)         // 256
#define NPAIR    (MSLICE / 2)            // 128
#define BLK_PER_BATCH (NCHUNK * TSPLIT)  // 128
#define NBLOCKS  (BATCH * BLK_PER_BATCH) // 1024

// Per-(batch, slice, source) partial min incl. s^2. One writer per slot. 2 MB.
__device__ float g_part[BATCH * TSPLIT * NSRC];
// Arrival counters per batch (int atomics: exact; self-reset each launch).
__device__ int g_count[BATCH];

typedef unsigned long long u64;

__device__ __forceinline__ u64 pack2(float lo, float hi) {
    u64 r;
    asm("mov.b64 %0, {%1, %2};" : "=l"(r) : "f"(lo), "f"(hi));
    return r;
}
__device__ __forceinline__ void unpack2(u64 v, float& lo, float& hi) {
    asm("mov.b64 {%0, %1}, %2;" : "=f"(lo), "=f"(hi) : "l"(v));
}
// packed dual-FMA: d = a*b + c on both 32-bit halves (SASS FFMA2)
__device__ __forceinline__ u64 ffma2(u64 a, u64 b, u64 c) {
    u64 d;
    asm("fma.rn.f32x2 %0, %1, %2, %3;" : "=l"(d) : "l"(a), "l"(b), "l"(c));
    return d;
}

__global__ void __launch_bounds__(TPB)
nn_min_kernel(const float* __restrict__ src, const float* __restrict__ tgt,
              float* __restrict__ out)
{
    // packed target pairs, 2 LDS.128 per pair-iter: {x01,y01} and {z01,w01}
    __shared__ ulonglong2 stxy[NPAIR], stzw[NPAIR];   // 4 KB
    __shared__ bool is_last;
    __shared__ float wsum[TPB / 32];

    const int bid   = blockIdx.x;
    const int slice = bid % TSPLIT;
    const int chunk = (bid / TSPLIT) % NCHUNK;
    const int b     = bid / BLK_PER_BATCH;
    const int tid   = threadIdx.x;

    // ---- stage this block's target slice (1 pair per thread) ----
    const float* tb = tgt + (size_t)b * 3 * MTGT + slice * MSLICE;
    for (int p = tid; p < NPAIR; p += TPB) {
        int m = 2 * p;
        float x0 = tb[m],            x1 = tb[m + 1];
        float y0 = tb[MTGT + m],     y1 = tb[MTGT + m + 1];
        float z0 = tb[2 * MTGT + m], z1 = tb[2 * MTGT + m + 1];
        float w0 = fmaf(x0, x0, fmaf(y0, y0, z0 * z0));
        float w1 = fmaf(x1, x1, fmaf(y1, y1, z1 * z1));
        stxy[p] = make_ulonglong2(pack2(x0, x1), pack2(y0, y1));
        stzw[p] = make_ulonglong2(pack2(z0, z1), pack2(w0, w1));
    }
    __syncthreads();

    // ---- load SPT source points, broadcast -2*s into packed halves ----
    const float* sb = src + (size_t)b * 3 * NSRC;
    const int n0 = chunk * SRC_PER_BLK + tid;

    u64 X[SPT], Y[SPT], Z[SPT];
    float s2[SPT], a0[SPT], a1[SPT];
    #pragma unroll
    for (int s = 0; s < SPT; s++) {
        int n = n0 + s * TPB;
        float sx = sb[n], sy = sb[NSRC + n], sz = sb[2 * NSRC + n];
        X[s] = pack2(-2.0f * sx, -2.0f * sx);
        Y[s] = pack2(-2.0f * sy, -2.0f * sy);
        Z[s] = pack2(-2.0f * sz, -2.0f * sz);
        s2[s] = fmaf(sx, sx, fmaf(sy, sy, sz * sz));
        a0[s] = 3.4e38f;
        a1[s] = 3.4e38f;
    }

    // ---- scan NPAIR target pairs; 2 targets x SPT sources per p ----
    #pragma unroll 8
    for (int p = 0; p < NPAIR; p++) {
        ulonglong2 xy = stxy[p];
        ulonglong2 zw = stzw[p];
        #pragma unroll
        for (int s = 0; s < SPT; s++) {
            u64 d = ffma2(xy.x, X[s], zw.y);
            d = ffma2(xy.y, Y[s], d);
            d = ffma2(zw.x, Z[s], d);
            float dl, dh;
            unpack2(d, dl, dh);
            a0[s] = fminf(a0[s], dl);
            a1[s] = fminf(a1[s], dh);
        }
    }

    // ---- per-slice partial store (coalesced), s^2 folded in ----
    float* gp = g_part + ((size_t)b * TSPLIT + slice) * NSRC;
    #pragma unroll
    for (int s = 0; s < SPT; s++)
        gp[n0 + s * TPB] = fminf(a0[s], a1[s]) + s2[s];

    // ---- last block of this batch reduces (threadfence-reduction pattern) ----
    __threadfence();
    __syncthreads();
    if (tid == 0) {
        int old = atomicAdd(&g_count[b], 1);
        is_last = (old == BLK_PER_BATCH - 1);
        if (is_last) {
            g_count[b] = 0;      // reset for next graph replay
            __threadfence();
        }
    }
    __syncthreads();
    if (!is_last) return;

    // Finisher: fixed-order, fixed-partition reduction -> deterministic.
    const float4* g4 = (const float4*)(g_part + (size_t)b * TSPLIT * NSRC);
    float sum = 0.0f;
    #pragma unroll
    for (int k = 0; k < (NSRC / 4) / TPB; k++) {     // 8 float4 groups/thread
        int idx = k * TPB + tid;
        float4 mn = g4[idx];
        #pragma unroll
        for (int sl = 1; sl < TSPLIT; sl++) {
            float4 v = g4[sl * (NSRC / 4) + idx];
            mn.x = fminf(mn.x, v.x);
            mn.y = fminf(mn.y, v.y);
            mn.z = fminf(mn.z, v.z);
            mn.w = fminf(mn.w, v.w);
        }
        sum += (mn.x + mn.y) + (mn.z + mn.w);
    }

    #pragma unroll
    for (int off = 16; off > 0; off >>= 1)
        sum += __shfl_down_sync(0xFFFFFFFFu, sum, off);

    const int lane = tid & 31, wid = tid >> 5;
    if (lane == 0) wsum[wid] = sum;
    __syncthreads();
    if (tid == 0) {
        float s = 0.0f;
        #pragma unroll
        for (int i = 0; i < TPB / 32; i++) s += wsum[i];
        out[b] = s * (1.0f / (float)(3 * NSRC));
    }
}

extern "C" void kernel_launch(void* const* d_in, const int* in_sizes, int n_in,
                              void* d_out, int out_size)
{
    const float* src = (const float*)d_in[0];   // [B,3,N]
    const float* tgt = (const float*)d_in[1];   // [B,3,M]
    float* out = (float*)d_out;                 // [B]

    nn_min_kernel<<<NBLOCKS, TPB>>>(src, tgt, out);
}

// round 13
// speedup vs baseline: 1.2588x; 1.2588x over previous
#include <cuda_runtime.h>
#include <math.h>

#define BATCH    8
#define NSRC     4096
#define MTGT     4096
#define TPB      128
#define SPT      4                       // sources per thread
#define SRC_PER_BLK (TPB * SPT)          // 512
#define NCHUNK   (NSRC / SRC_PER_BLK)    // 8
#define TSPLIT   8                       // target slices
#define MSLICE   (MTGT / TSPLIT)         // 512
#define NPAIR    (MSLICE / 2)            // 256
#define NBLOCKS  (BATCH * NCHUNK * TSPLIT) // 512

// Per-(batch, slice, source) partial min incl. s^2. One writer per slot.
__device__ float g_part[BATCH * TSPLIT * NSRC];
// Stage-1 reduction partials: [b][part], 8 parts per batch.
__device__ float g_psum[BATCH * 8];

typedef unsigned long long u64;

__device__ __forceinline__ u64 pack2(float lo, float hi) {
    u64 r;
    asm("mov.b64 %0, {%1, %2};" : "=l"(r) : "f"(lo), "f"(hi));
    return r;
}
__device__ __forceinline__ void unpack2(u64 v, float& lo, float& hi) {
    asm("mov.b64 {%0, %1}, %2;" : "=f"(lo), "=f"(hi) : "l"(v));
}
// packed dual-FMA: d = a*b + c on both 32-bit halves (SASS FFMA2)
__device__ __forceinline__ u64 ffma2(u64 a, u64 b, u64 c) {
    u64 d;
    asm("fma.rn.f32x2 %0, %1, %2, %3;" : "=l"(d) : "l"(a), "l"(b), "l"(c));
    return d;
}

__global__ void __launch_bounds__(TPB)
nn_min_kernel(const float* __restrict__ src, const float* __restrict__ tgt)
{
    // SoA of packed target pairs: one LDS.64 -> aligned register pair, no MOVs
    __shared__ u64 stx[NPAIR], sty[NPAIR], stz[NPAIR], stw[NPAIR]; // 8 KB

    const int bid   = blockIdx.x;
    const int slice = bid % TSPLIT;
    const int chunk = (bid / TSPLIT) % NCHUNK;
    const int b     = bid / (TSPLIT * NCHUNK);
    const int tid   = threadIdx.x;

    // ---- stage this block's target slice ----
    const float* tb = tgt + (size_t)b * 3 * MTGT + slice * MSLICE;
    for (int p = tid; p < NPAIR; p += TPB) {
        int m = 2 * p;
        float x0 = tb[m],            x1 = tb[m + 1];
        float y0 = tb[MTGT + m],     y1 = tb[MTGT + m + 1];
        float z0 = tb[2 * MTGT + m], z1 = tb[2 * MTGT + m + 1];
        float w0 = fmaf(x0, x0, fmaf(y0, y0, z0 * z0));
        float w1 = fmaf(x1, x1, fmaf(y1, y1, z1 * z1));
        stx[p] = pack2(x0, x1);
        sty[p] = pack2(y0, y1);
        stz[p] = pack2(z0, z1);
        stw[p] = pack2(w0, w1);
    }
    __syncthreads();

    // ---- load SPT source points, broadcast -2*s into packed halves ----
    const float* sb = src + (size_t)b * 3 * NSRC;
    const int n0 = chunk * SRC_PER_BLK + tid;

    u64 X[SPT], Y[SPT], Z[SPT];
    float s2[SPT], a0[SPT], a1[SPT];
    #pragma unroll
    for (int s = 0; s < SPT; s++) {
        int n = n0 + s * TPB;
        float sx = sb[n], sy = sb[NSRC + n], sz = sb[2 * NSRC + n];
        X[s] = pack2(-2.0f * sx, -2.0f * sx);
        Y[s] = pack2(-2.0f * sy, -2.0f * sy);
        Z[s] = pack2(-2.0f * sz, -2.0f * sz);
        s2[s] = fmaf(sx, sx, fmaf(sy, sy, sz * sz));
        a0[s] = 3.4e38f;
        a1[s] = 3.4e38f;
    }

    // ---- scan NPAIR target pairs; 2 targets x SPT sources per p ----
    #pragma unroll 8
    for (int p = 0; p < NPAIR; p++) {
        u64 x01 = stx[p];
        u64 y01 = sty[p];
        u64 z01 = stz[p];
        u64 w01 = stw[p];
        #pragma unroll
        for (int s = 0; s < SPT; s++) {
            u64 d = ffma2(x01, X[s], w01);
            d = ffma2(y01, Y[s], d);
            d = ffma2(z01, Z[s], d);
            float dl, dh;
            unpack2(d, dl, dh);
            a0[s] = fminf(a0[s], dl);
            a1[s] = fminf(a1[s], dh);
        }
    }

    // ---- plain per-slice store (coalesced across tid), s^2 folded in ----
    float* gp = g_part + ((size_t)b * TSPLIT + slice) * NSRC;
    #pragma unroll
    for (int s = 0; s < SPT; s++)
        gp[n0 + s * TPB] = fminf(a0[s], a1[s]) + s2[s];
}

// ---- stage 1: 64 blocks (8 per batch), each reduces 512 sources ----
#define F1TPB 128

__global__ void __launch_bounds__(F1TPB)
finish1_kernel()
{
    const int blk  = blockIdx.x;       // 0..63
    const int b    = blk >> 3;
    const int part = blk & 7;
    const int tid  = threadIdx.x;

    const float4* gp = (const float4*)(g_part + (size_t)b * TSPLIT * NSRC);
    const int idx = part * F1TPB + tid;   // float4 index within a slice (0..1023)

    float4 mn = gp[idx];
    #pragma unroll
    for (int k = 1; k < TSPLIT; k++) {
        float4 v = gp[k * (NSRC / 4) + idx];
        mn.x = fminf(mn.x, v.x);
        mn.y = fminf(mn.y, v.y);
        mn.z = fminf(mn.z, v.z);
        mn.w = fminf(mn.w, v.w);
    }
    float sum = (mn.x + mn.y) + (mn.z + mn.w);

    #pragma unroll
    for (int off = 16; off > 0; off >>= 1)
        sum += __shfl_down_sync(0xFFFFFFFFu, sum, off);

    __shared__ float wsum[F1TPB / 32];
    const int lane = tid & 31, wid = tid >> 5;
    if (lane == 0) wsum[wid] = sum;
    __syncthreads();
    if (tid == 0) {
        float s = 0.0f;
        #pragma unroll
        for (int i = 0; i < F1TPB / 32; i++) s += wsum[i];
        g_psum[blk] = s;
    }
}

// ---- stage 2: tiny, deterministic ----
__global__ void finish2_kernel(float* __restrict__ out)
{
    const int b = threadIdx.x;
    if (b < BATCH) {
        float s = 0.0f;
        #pragma unroll
        for (int i = 0; i < 8; i++) s += g_psum[b * 8 + i];
        out[b] = s * (1.0f / (float)(3 * NSRC));
    }
}

extern "C" void kernel_launch(void* const* d_in, const int* in_sizes, int n_in,
                              void* d_out, int out_size)
{
    const float* src = (const float*)d_in[0];   // [B,3,N]
    const float* tgt = (const float*)d_in[1];   // [B,3,M]
    float* out = (float*)d_out;                 // [B]

    nn_min_kernel<<<NBLOCKS, TPB>>>(src, tgt);
    finish1_kernel<<<BATCH * 8, F1TPB>>>();
    finish2_kernel<<<1, 32>>>(out);
}